// round 7
// baseline (speedup 1.0000x reference)
#include <cuda_runtime.h>

// 2D Haar DWT, fp32, x:[16,64,512,512] -> out:[4,16,64,256,256]
// Pure streaming, DRAM-bound. Best: R6 one-shot dense 2-col (307.0us, 88.4% DRAM).
// R7: one-shot grid + dense 4 output cols/thread — lane reads 32B contiguous
// per input row (2 consecutive LDG.128), writes STG.128 per band (512B
// contiguous per warp per band vs R6's 256B). Bigger read/write bursts ->
// better DRAM page locality; thread count halves vs R6 but regs ~28 keeps
// occupancy high (R1 geometry ran fine at 76%).
//
//   ll = 0.5*(a+b+c+d)   lh = 0.5*(a+b-c-d)
//   hl = 0.5*(a-b+c-d)   hh = 0.5*(a-b-c+d)

static constexpr int W_IN  = 512;
static constexpr int W_OUT = 256;
static constexpr int H_OUT = 256;
static constexpr int PLANES = 16 * 64;                                  // 1024
static constexpr long long IN_PLANE  = (long long)W_IN * 512;           // 262144
static constexpr long long OUT_PLANE = (long long)W_OUT * H_OUT;        // 65536
static constexpr long long BAND_STRIDE = (long long)PLANES * OUT_PLANE; // 67,108,864

__global__ __launch_bounds__(256) void haar_dwt_kernel(
    const float* __restrict__ x, float* __restrict__ out)
{
    unsigned idx = blockIdx.x * 256u + threadIdx.x;   // 0 .. 16,777,215
    unsigned tx = idx & 63u;           // 4-col group (input cols 8tx..8tx+7)
    unsigned h  = (idx >> 6) & 255u;   // output row
    unsigned p  = idx >> 14;           // plane 0..1023

    // Dense: thread loads 8 consecutive floats (32B) from each of rows 2h, 2h+1.
    const float* base = x + (size_t)p * IN_PLANE + (size_t)(2u * h) * W_IN + tx * 8u;
    float4 r0a = *reinterpret_cast<const float4*>(base);
    float4 r0b = *reinterpret_cast<const float4*>(base + 4);
    float4 r1a = *reinterpret_cast<const float4*>(base + W_IN);
    float4 r1b = *reinterpret_cast<const float4*>(base + W_IN + 4);

    float4 ll, lh, hl, hh;
    {
        float sT = r0a.x + r0a.y, dT = r0a.x - r0a.y;
        float sB = r1a.x + r1a.y, dB = r1a.x - r1a.y;
        ll.x = 0.5f * (sT + sB); lh.x = 0.5f * (sT - sB);
        hl.x = 0.5f * (dT + dB); hh.x = 0.5f * (dT - dB);
    }
    {
        float sT = r0a.z + r0a.w, dT = r0a.z - r0a.w;
        float sB = r1a.z + r1a.w, dB = r1a.z - r1a.w;
        ll.y = 0.5f * (sT + sB); lh.y = 0.5f * (sT - sB);
        hl.y = 0.5f * (dT + dB); hh.y = 0.5f * (dT - dB);
    }
    {
        float sT = r0b.x + r0b.y, dT = r0b.x - r0b.y;
        float sB = r1b.x + r1b.y, dB = r1b.x - r1b.y;
        ll.z = 0.5f * (sT + sB); lh.z = 0.5f * (sT - sB);
        hl.z = 0.5f * (dT + dB); hh.z = 0.5f * (dT - dB);
    }
    {
        float sT = r0b.z + r0b.w, dT = r0b.z - r0b.w;
        float sB = r1b.z + r1b.w, dB = r1b.z - r1b.w;
        ll.w = 0.5f * (sT + sB); lh.w = 0.5f * (sT - sB);
        hl.w = 0.5f * (dT + dB); hh.w = 0.5f * (dT - dB);
    }

    float* o = out + (size_t)p * OUT_PLANE + (size_t)h * W_OUT + tx * 4u;
    *reinterpret_cast<float4*>(o)                   = ll;
    *reinterpret_cast<float4*>(o + BAND_STRIDE)     = lh;
    *reinterpret_cast<float4*>(o + 2 * BAND_STRIDE) = hl;
    *reinterpret_cast<float4*>(o + 3 * BAND_STRIDE) = hh;
}

extern "C" void kernel_launch(void* const* d_in, const int* in_sizes, int n_in,
                              void* d_out, int out_size) {
    const float* x = (const float*)d_in[0];
    float* out = (float*)d_out;
    // total threads = 1024 planes * 256 rows * 64 groups = 16,777,216
    unsigned total = (unsigned)PLANES * H_OUT * (W_OUT / 4);
    haar_dwt_kernel<<<total / 256, 256>>>(x, out);
}

// round 8
// speedup vs baseline: 1.0046x; 1.0046x over previous
#include <cuda_runtime.h>

// 2D Haar DWT, fp32, x:[16,64,512,512] -> out:[4,16,64,256,256]
// Pure streaming, DRAM-bound. Best: R6 (dense 2-col/thread, block=256,
// 307.0us, 88.4% DRAM, occ 78.7%).
// Scan over per-thread width {2,4-dense,4-strided,8} shows finer granularity
// wins: more CTAs in the one-shot drain/refill pipeline. R8: same body as R6,
// CTA size 256 -> 128 (262,144 CTAs; 16 CTAs/SM) to tighten the per-CTA
// drain/refill quantum further.
//
//   ll = 0.5*(a+b+c+d)   lh = 0.5*(a+b-c-d)
//   hl = 0.5*(a-b+c-d)   hh = 0.5*(a-b-c+d)

static constexpr int W_IN  = 512;
static constexpr int W_OUT = 256;
static constexpr int H_OUT = 256;
static constexpr int PLANES = 16 * 64;                                  // 1024
static constexpr long long IN_PLANE  = (long long)W_IN * 512;           // 262144
static constexpr long long OUT_PLANE = (long long)W_OUT * H_OUT;        // 65536
static constexpr long long BAND_STRIDE = (long long)PLANES * OUT_PLANE; // 67,108,864

__global__ __launch_bounds__(128) void haar_dwt_kernel(
    const float* __restrict__ x, float* __restrict__ out)
{
    unsigned idx = blockIdx.x * 128u + threadIdx.x;   // 0 .. 33,554,431
    unsigned tx = idx & 127u;          // 2-col group (input cols 4tx..4tx+3)
    unsigned h  = (idx >> 7) & 255u;   // output row
    unsigned p  = idx >> 15;           // plane 0..1023

    // Dense: thread loads 4 consecutive floats (16B) from each of rows 2h, 2h+1.
    const float* base = x + (size_t)p * IN_PLANE + (size_t)(2u * h) * W_IN + tx * 4u;
    float4 c0 = *reinterpret_cast<const float4*>(base);
    float4 c1 = *reinterpret_cast<const float4*>(base + W_IN);

    float2 ll, lh, hl, hh;
    {
        float sT = c0.x + c0.y, dT = c0.x - c0.y;
        float sB = c1.x + c1.y, dB = c1.x - c1.y;
        ll.x = 0.5f * (sT + sB); lh.x = 0.5f * (sT - sB);
        hl.x = 0.5f * (dT + dB); hh.x = 0.5f * (dT - dB);
    }
    {
        float sT = c0.z + c0.w, dT = c0.z - c0.w;
        float sB = c1.z + c1.w, dB = c1.z - c1.w;
        ll.y = 0.5f * (sT + sB); lh.y = 0.5f * (sT - sB);
        hl.y = 0.5f * (dT + dB); hh.y = 0.5f * (dT - dB);
    }

    float* o = out + (size_t)p * OUT_PLANE + (size_t)h * W_OUT + tx * 2u;
    *reinterpret_cast<float2*>(o)                   = ll;
    *reinterpret_cast<float2*>(o + BAND_STRIDE)     = lh;
    *reinterpret_cast<float2*>(o + 2 * BAND_STRIDE) = hl;
    *reinterpret_cast<float2*>(o + 3 * BAND_STRIDE) = hh;
}

extern "C" void kernel_launch(void* const* d_in, const int* in_sizes, int n_in,
                              void* d_out, int out_size) {
    const float* x = (const float*)d_in[0];
    float* out = (float*)d_out;
    // total threads = 1024 planes * 256 rows * 128 groups = 33,554,432
    unsigned total = (unsigned)PLANES * H_OUT * (W_OUT / 2);
    haar_dwt_kernel<<<total / 128, 128>>>(x, out);
}